// round 14
// baseline (speedup 1.0000x reference)
#include <cuda_runtime.h>
#include <cuda_fp16.h>
#include <cstdint>

#define BROWS 4096
#define INF   1024
#define OUTF  1024
#define KDIM  9216          // 1024 silu cols + 8192 basis cols (block K layout)

// GEMM config (round-8 measured-best): persistent, 128x64 tiles, split-K=4
#define TMd 128
#define TNd 64
#define KSPLIT 4
#define KPER  (KDIM / KSPLIT)   // 2304
#define CHUNK 64                // k-chunk in halfs
#define ITERSU (KPER / CHUNK)   // 36
#define STAGES 3
#define SROW_H 72               // smem row stride in halfs (144 B, conflict-free)
#define A_BYTES (TMd * SROW_H * 2)        // 18432
#define B_BYTES (TNd * SROW_H * 2)        // 9216
#define STAGE_BYTES (A_BYTES + B_BYTES)   // 27648
#define SMEM_TOTAL (STAGES * STAGE_BYTES + 16)  // 82960
#define NUNITS ((BROWS / TMd) * (OUTF / TNd) * KSPLIT)  // 2048
#define GCTAS 296
#define GTHREADS 128

// Scratch (static device globals — no runtime allocation)
__device__ __align__(256) __half g_act[(size_t)BROWS * KDIM];   // 75 MB
__device__ __align__(256) __half g_w[(size_t)OUTF * KDIM];      // 19 MB
__device__ __align__(256) __half g_part[(size_t)KSPLIT * BROWS * OUTF];  // 33.5 MB
__device__ int g_ctr;

__device__ __forceinline__ uint2 f4toh4(float4 v) {
    __half2 a = __floats2half2_rn(v.x, v.y);
    __half2 b = __floats2half2_rn(v.z, v.w);
    uint2 r;
    r.x = *(uint32_t*)&a;
    r.y = *(uint32_t*)&b;
    return r;
}

// ---------------------------------------------------------------------------
// Kernel 1 (merged prep, block-K layout, zero smem staging):
//  blocks [0, 4096): Act row b: [0,1024)=silu(x[b,:]), [1024+8i+q]=basis_q(x[b,i])
//  blocks [4096, 5120): W row o: [0,1024)=bw[o,:], [1024+8i+q]=sw[o,i,q]
//  All loads float4, all stores uint2/uint4, fully coalesced.
// ---------------------------------------------------------------------------
#define ACT_BLOCKS BROWS    // one block per batch row
#define W_BLOCKS   OUTF     // one block per output row

__global__ __launch_bounds__(256) void prep_kernel(const float* __restrict__ x,
                                                   const float* __restrict__ grid,
                                                   const float* __restrict__ bw,
                                                   const float* __restrict__ sw) {
    const int tid = threadIdx.x;
    const int bid = blockIdx.x;

    if (bid < ACT_BLOCKS) {
        const int b = bid;
        const float g0   = __ldg(grid);
        const float invh = 11.f / (__ldg(grid + 11) - g0);

        float4 xv4 = ((const float4*)x)[b * 256 + tid];   // features 4t..4t+3
        float xs[4] = {xv4.x, xv4.y, xv4.z, xv4.w};

        __half sil[4];
        uint4  bas[4];
#pragma unroll
        for (int e = 0; e < 4; e++) {
            float xv = xs[e];
            float u = (xv - g0) * invh;
            float jf = floorf(u);
            int j = (int)jf;
            j = j < 0 ? 0 : (j > 10 ? 10 : j);
            float f = u - (float)j;
            float f2 = f * f, f3 = f2 * f;
            float om = 1.f - f;
            float p0 = f3 * (1.f / 6.f);                 // basis q = j
            float p3 = om * om * om * (1.f / 6.f);       // basis q = j-3
            float p2 = 0.5f * f3 - f2 + (4.f / 6.f);     // basis q = j-2
            float p1 = 1.f - p0 - p2 - p3;               // basis q = j-1

            sil[e] = __float2half_rn(xv * __frcp_rn(1.f + __expf(-xv)));

            // branchless pack of the 8 basis values (4 nonzero at q=j-3..j)
#define BV(q) ((j == (q)) ? p0 : (j == (q) + 1) ? p1 : (j == (q) + 2) ? p2 \
               : (j == (q) + 3) ? p3 : 0.f)
            __half2 h01 = __floats2half2_rn(BV(0), BV(1));
            __half2 h23 = __floats2half2_rn(BV(2), BV(3));
            __half2 h45 = __floats2half2_rn(BV(4), BV(5));
            __half2 h67 = __floats2half2_rn(BV(6), BV(7));
#undef BV
            bas[e].x = *(uint32_t*)&h01;
            bas[e].y = *(uint32_t*)&h23;
            bas[e].z = *(uint32_t*)&h45;
            bas[e].w = *(uint32_t*)&h67;
        }

        __half* row = g_act + (size_t)b * KDIM;
        // silu: 4 consecutive halfs per thread (uint2, coalesced)
        uint2 sp;
        __half2 s01 = __halves2half2(sil[0], sil[1]);
        __half2 s23 = __halves2half2(sil[2], sil[3]);
        sp.x = *(uint32_t*)&s01;
        sp.y = *(uint32_t*)&s23;
        ((uint2*)row)[tid] = sp;
        // basis: 4 uint4 per thread at 64B-contiguous region (coalesced)
        uint4* bdst = (uint4*)(row + 1024) + tid * 4;
        bdst[0] = bas[0]; bdst[1] = bas[1]; bdst[2] = bas[2]; bdst[3] = bas[3];
    } else {
        const int o = bid - ACT_BLOCKS;
        if (o == 0 && tid == 0) g_ctr = 0;   // reset GEMM work queue
        __half* wrow = g_w + (size_t)o * KDIM;

        // bw row: 1024 floats = 256 float4; 1 per thread
        float4 v = ((const float4*)(bw + (size_t)o * 1024))[tid];
        ((uint2*)wrow)[tid] = f4toh4(v);

        // sw row: 8192 floats = 2048 float4; 8 per thread
        const float4* swr = (const float4*)(sw + (size_t)o * 8192);
        uint2* wd = (uint2*)(wrow + 1024);
#pragma unroll
        for (int k = 0; k < 8; k++) {
            float4 s4 = swr[tid + k * 256];
            wd[tid + k * 256] = f4toh4(s4);
        }
    }
}

// ---------------------------------------------------------------------------
// Kernel 2: fp16 mma.sync GEMM, persistent split-K (round-8 config).
// 296 CTAs (2/SM), 2048 units, 4 warps (2m x 2n), warp tile 64x32.
// ---------------------------------------------------------------------------
__device__ __forceinline__ void issue_stage(uint32_t sb, int stage, int it,
                                            int m0, int n0, int kb0, int tid) {
    const int kk = kb0 + it * CHUNK;
    const uint32_t sA = sb + stage * STAGE_BYTES;
    const uint32_t sB = sA + A_BYTES;
#pragma unroll
    for (int j = 0; j < 12; j++) {            // 192 rows x 8 chunks = 1536 copies
        int id  = tid + j * GTHREADS;         // 0..1535
        int row = id >> 3, c = id & 7;
        if (row < TMd) {
            const __half* ga = &g_act[(size_t)(m0 + row) * KDIM + kk + c * 8];
            asm volatile("cp.async.cg.shared.global [%0], [%1], 16;"
                         :: "r"(sA + (uint32_t)(row * SROW_H + c * 8) * 2), "l"(ga));
        } else {
            int r2 = row - TMd;
            const __half* gb = &g_w[(size_t)(n0 + r2) * KDIM + kk + c * 8];
            asm volatile("cp.async.cg.shared.global [%0], [%1], 16;"
                         :: "r"(sB + (uint32_t)(r2 * SROW_H + c * 8) * 2), "l"(gb));
        }
    }
}

__global__ __launch_bounds__(GTHREADS, 2) void gemm_kernel() {
    extern __shared__ __align__(16) char smem[];
    const uint32_t sb = (uint32_t)__cvta_generic_to_shared(smem);
    int* s_unit = (int*)(smem + STAGES * STAGE_BYTES);
    const int tid = threadIdx.x;
    const int wid = tid >> 5, lane = tid & 31;
    const int g = lane >> 2, t = lane & 3;
    const int wm = wid >> 1, wn = wid & 1;     // 2 x 2 warp grid

    for (;;) {
        if (tid == 0) *s_unit = atomicAdd(&g_ctr, 1);
        __syncthreads();
        const int u = *s_unit;
        if (u >= NUNITS) break;
        const int m0  = (u >> 6) * TMd;         // 16 consecutive units share A strip
        const int ks  = (u >> 4) & 3;
        const int n0  = (u & 15) * TNd;
        const int kb0 = ks * KPER;

        float acc[4][4][4];
#pragma unroll
        for (int i = 0; i < 4; i++)
#pragma unroll
            for (int jj = 0; jj < 4; jj++)
#pragma unroll
                for (int r = 0; r < 4; r++) acc[i][jj][r] = 0.f;

#pragma unroll
        for (int s = 0; s < STAGES - 1; s++) {
            issue_stage(sb, s, s, m0, n0, kb0, tid);
            asm volatile("cp.async.commit_group;");
        }

        const int aRow = wm * 64 + g;
        const int bRow = wn * 32 + g;

        for (int it = 0; it < ITERSU; ++it) {
            asm volatile("cp.async.wait_group %0;" :: "n"(STAGES - 2));
            __syncthreads();
            if (it + STAGES - 1 < ITERSU)
                issue_stage(sb, (it + STAGES - 1) % STAGES, it + STAGES - 1,
                            m0, n0, kb0, tid);
            asm volatile("cp.async.commit_group;");

            const int buf = it % STAGES;
            const __half* As = (const __half*)(smem + buf * STAGE_BYTES);
            const __half* Bs = (const __half*)(smem + buf * STAGE_BYTES + A_BYTES);

#pragma unroll
            for (int kb = 0; kb < CHUNK; kb += 16) {
                uint32_t af[4][4], bf[4][2];
#pragma unroll
                for (int mi = 0; mi < 4; mi++) {
                    int r = aRow + mi * 16;
                    af[mi][0] = *(const uint32_t*)&As[r * SROW_H + kb + 2 * t];
                    af[mi][1] = *(const uint32_t*)&As[(r + 8) * SROW_H + kb + 2 * t];
                    af[mi][2] = *(const uint32_t*)&As[r * SROW_H + kb + 2 * t + 8];
                    af[mi][3] = *(const uint32_t*)&As[(r + 8) * SROW_H + kb + 2 * t + 8];
                }
#pragma unroll
                for (int ni = 0; ni < 4; ni++) {
                    int r = bRow + ni * 8;
                    bf[ni][0] = *(const uint32_t*)&Bs[r * SROW_H + kb + 2 * t];
                    bf[ni][1] = *(const uint32_t*)&Bs[r * SROW_H + kb + 2 * t + 8];
                }
#pragma unroll
                for (int mi = 0; mi < 4; mi++)
#pragma unroll
                    for (int ni = 0; ni < 4; ni++) {
                        asm volatile(
                            "mma.sync.aligned.m16n8k16.row.col.f32.f16.f16.f32 "
                            "{%0,%1,%2,%3}, {%4,%5,%6,%7}, {%8,%9}, {%0,%1,%2,%3};"
                            : "+f"(acc[mi][ni][0]), "+f"(acc[mi][ni][1]),
                              "+f"(acc[mi][ni][2]), "+f"(acc[mi][ni][3])
                            : "r"(af[mi][0]), "r"(af[mi][1]),
                              "r"(af[mi][2]), "r"(af[mi][3]),
                              "r"(bf[ni][0]), "r"(bf[ni][1]));
                    }
            }
        }

        // Epilogue: write fp16 partial tile to g_part[ks]
        __half* part = g_part + (size_t)ks * BROWS * OUTF;
#pragma unroll
        for (int mi = 0; mi < 4; mi++)
#pragma unroll
            for (int ni = 0; ni < 4; ni++) {
                int row = m0 + wm * 64 + mi * 16 + g;
                int col = n0 + wn * 32 + ni * 8 + 2 * t;
                __half2 h0 = __floats2half2_rn(acc[mi][ni][0], acc[mi][ni][1]);
                __half2 h1 = __floats2half2_rn(acc[mi][ni][2], acc[mi][ni][3]);
                *(__half2*)&part[(size_t)row * OUTF + col]       = h0;
                *(__half2*)&part[(size_t)(row + 8) * OUTF + col] = h1;
            }
        // next-unit top-of-loop barrier protects smem stage reuse
    }
}

// ---------------------------------------------------------------------------
// Kernel 3: reduce fp16 partials -> fp32 out (convert before summing)
// ---------------------------------------------------------------------------
#define PL_U4 ((BROWS * OUTF) / 8)   // uint4 (8 halfs) per plane = 524288
__global__ __launch_bounds__(256) void reduce_kernel(float* __restrict__ out) {
    int i = blockIdx.x * 256 + threadIdx.x;   // group of 8 output elems
    const uint4* p = (const uint4*)g_part;
    uint4 a = p[i], b = p[i + PL_U4], c = p[i + 2 * PL_U4], d = p[i + 3 * PL_U4];

    float4 r0, r1;
    {
        float2 fa = __half22float2(*(__half2*)&a.x), fb = __half22float2(*(__half2*)&b.x);
        float2 fc = __half22float2(*(__half2*)&c.x), fd = __half22float2(*(__half2*)&d.x);
        r0.x = (fa.x + fb.x) + (fc.x + fd.x);
        r0.y = (fa.y + fb.y) + (fc.y + fd.y);
    }
    {
        float2 fa = __half22float2(*(__half2*)&a.y), fb = __half22float2(*(__half2*)&b.y);
        float2 fc = __half22float2(*(__half2*)&c.y), fd = __half22float2(*(__half2*)&d.y);
        r0.z = (fa.x + fb.x) + (fc.x + fd.x);
        r0.w = (fa.y + fb.y) + (fc.y + fd.y);
    }
    {
        float2 fa = __half22float2(*(__half2*)&a.z), fb = __half22float2(*(__half2*)&b.z);
        float2 fc = __half22float2(*(__half2*)&c.z), fd = __half22float2(*(__half2*)&d.z);
        r1.x = (fa.x + fb.x) + (fc.x + fd.x);
        r1.y = (fa.y + fb.y) + (fc.y + fd.y);
    }
    {
        float2 fa = __half22float2(*(__half2*)&a.w), fb = __half22float2(*(__half2*)&b.w);
        float2 fc = __half22float2(*(__half2*)&c.w), fd = __half22float2(*(__half2*)&d.w);
        r1.z = (fa.x + fb.x) + (fc.x + fd.x);
        r1.w = (fa.y + fb.y) + (fc.y + fd.y);
    }
    ((float4*)out)[2 * i]     = r0;
    ((float4*)out)[2 * i + 1] = r1;
}

// ---------------------------------------------------------------------------
extern "C" void kernel_launch(void* const* d_in, const int* in_sizes, int n_in,
                              void* d_out, int out_size) {
    const float* x    = (const float*)d_in[0];
    const float* bw   = (const float*)d_in[1];
    const float* sw   = (const float*)d_in[2];
    const float* grid = (const float*)d_in[3];
    float* out = (float*)d_out;

    cudaFuncSetAttribute(gemm_kernel, cudaFuncAttributeMaxDynamicSharedMemorySize,
                         SMEM_TOTAL);

    prep_kernel<<<ACT_BLOCKS + W_BLOCKS, 256>>>(x, grid, bw, sw);
    gemm_kernel<<<GCTAS, GTHREADS, SMEM_TOTAL>>>();
    reduce_kernel<<<PL_U4 / 256, 256>>>(out);
}

// round 17
// speedup vs baseline: 1.0391x; 1.0391x over previous
#include <cuda_runtime.h>
#include <cuda_fp16.h>
#include <cstdint>

#define BROWS 4096
#define INF   1024
#define OUTF  1024
#define KDIM  9216          // 1024 silu cols + 8192 basis cols (block K layout)

// GEMM config (round-8 measured-best): persistent, 128x64 tiles, split-K=4
#define TMd 128
#define TNd 64
#define KSPLIT 4
#define KPER  (KDIM / KSPLIT)   // 2304
#define CHUNK 64                // k-chunk in halfs
#define ITERSU (KPER / CHUNK)   // 36
#define STAGES 3
#define SROW_H 72               // smem row stride in halfs (144 B, conflict-free)
#define A_BYTES (TMd * SROW_H * 2)        // 18432
#define B_BYTES (TNd * SROW_H * 2)        // 9216
#define STAGE_BYTES (A_BYTES + B_BYTES)   // 27648
#define SMEM_TOTAL (STAGES * STAGE_BYTES + 16)  // 82960
#define NUNITS ((BROWS / TMd) * (OUTF / TNd) * KSPLIT)  // 2048
#define GCTAS 296
#define GTHREADS 128

// Scratch (static device globals — no runtime allocation)
__device__ __align__(256) __half g_act[(size_t)BROWS * KDIM];   // 75 MB
__device__ __align__(256) __half g_w[(size_t)OUTF * KDIM];      // 19 MB
__device__ __align__(256) __half g_part[(size_t)KSPLIT * BROWS * OUTF];  // 33.5 MB
__device__ int g_ctr;

__device__ __forceinline__ uint2 f4toh4(float4 v) {
    __half2 a = __floats2half2_rn(v.x, v.y);
    __half2 b = __floats2half2_rn(v.z, v.w);
    uint2 r;
    r.x = *(uint32_t*)&a;
    r.y = *(uint32_t*)&b;
    return r;
}

// ---------------------------------------------------------------------------
// Kernel 1 (merged prep, block-K layout):
//  blocks [0, 4096): Act row b: [0,1024)=silu(x[b,:]), [1024+8i+q]=basis_q(x[b,i])
//    basis via zero-filled smem tile + 4 guarded scatter stores per element
//    (round-13's proven pack strategy), silu register->uint2 direct.
//  blocks [4096, 5120): W row o: [0,1024)=bw[o,:], [1024+8i+q]=sw[o,i,q]
//    pure register streaming conversion (no smem).
// ---------------------------------------------------------------------------
#define ACT_BLOCKS BROWS    // one block per batch row
#define W_BLOCKS   OUTF     // one block per output row

__global__ __launch_bounds__(256) void prep_kernel(const float* __restrict__ x,
                                                   const float* __restrict__ grid,
                                                   const float* __restrict__ bw,
                                                   const float* __restrict__ sw) {
    __shared__ __half sbas[1024 * 8];   // 16 KB basis staging (act branch only)
    const int tid = threadIdx.x;
    const int bid = blockIdx.x;

    if (bid < ACT_BLOCKS) {
        const int b = bid;
        const float g0   = __ldg(grid);
        const float invh = 11.f / (__ldg(grid + 11) - g0);

        float4 xv4 = ((const float4*)x)[b * 256 + tid];   // features 4t..4t+3
        float xs[4] = {xv4.x, xv4.y, xv4.z, xv4.w};

        // zero-fill basis tile: 1024 uint4, 4 per thread
        uint4 z; z.x = z.y = z.z = z.w = 0u;
#pragma unroll
        for (int i = 0; i < 4; i++) ((uint4*)sbas)[tid + i * 256] = z;
        __syncthreads();

        __half sil[4];
#pragma unroll
        for (int e = 0; e < 4; e++) {
            float xv = xs[e];
            float u = (xv - g0) * invh;
            float jf = floorf(u);
            int j = (int)jf;
            j = j < 0 ? 0 : (j > 10 ? 10 : j);
            float f = u - (float)j;
            float f2 = f * f, f3 = f2 * f;
            float om = 1.f - f;
            float p0 = f3 * (1.f / 6.f);                 // basis q = j
            float p3 = om * om * om * (1.f / 6.f);       // basis q = j-3
            float p2 = 0.5f * f3 - f2 + (4.f / 6.f);     // basis q = j-2
            float p1 = 1.f - p0 - p2 - p3;               // basis q = j-1

            sil[e] = __float2half_rn(xv * __frcp_rn(1.f + __expf(-xv)));

            __half* o = sbas + (tid * 4 + e) * 8;
            if (j < 8)               o[j]     = __float2half_rn(p0);
            if (j >= 1 && j - 1 < 8) o[j - 1] = __float2half_rn(p1);
            if (j >= 2 && j - 2 < 8) o[j - 2] = __float2half_rn(p2);
            if (j >= 3 && j - 3 < 8) o[j - 3] = __float2half_rn(p3);
        }
        __syncthreads();

        __half* row = g_act + (size_t)b * KDIM;
        // silu: 4 consecutive halfs per thread (uint2, coalesced)
        uint2 sp;
        __half2 s01 = __halves2half2(sil[0], sil[1]);
        __half2 s23 = __halves2half2(sil[2], sil[3]);
        sp.x = *(uint32_t*)&s01;
        sp.y = *(uint32_t*)&s23;
        ((uint2*)row)[tid] = sp;
        // basis: copy out 1024 uint4 coalesced
        uint4* bdst = (uint4*)(row + 1024);
        const uint4* bsrc = (const uint4*)sbas;
#pragma unroll
        for (int i = 0; i < 4; i++) bdst[tid + i * 256] = bsrc[tid + i * 256];
    } else {
        const int o = bid - ACT_BLOCKS;
        if (o == 0 && tid == 0) g_ctr = 0;   // reset GEMM work queue
        __half* wrow = g_w + (size_t)o * KDIM;

        // bw row: 1024 floats = 256 float4; 1 per thread
        float4 v = ((const float4*)(bw + (size_t)o * 1024))[tid];
        ((uint2*)wrow)[tid] = f4toh4(v);

        // sw row: 8192 floats = 2048 float4; 8 per thread
        const float4* swr = (const float4*)(sw + (size_t)o * 8192);
        uint2* wd = (uint2*)(wrow + 1024);
#pragma unroll
        for (int k = 0; k < 8; k++) {
            float4 s4 = swr[tid + k * 256];
            wd[tid + k * 256] = f4toh4(s4);
        }
    }
}

// ---------------------------------------------------------------------------
// Kernel 2: fp16 mma.sync GEMM, persistent split-K (round-8 config).
// 296 CTAs (2/SM), 2048 units, 4 warps (2m x 2n), warp tile 64x32.
// ---------------------------------------------------------------------------
__device__ __forceinline__ void issue_stage(uint32_t sb, int stage, int it,
                                            int m0, int n0, int kb0, int tid) {
    const int kk = kb0 + it * CHUNK;
    const uint32_t sA = sb + stage * STAGE_BYTES;
    const uint32_t sB = sA + A_BYTES;
#pragma unroll
    for (int j = 0; j < 12; j++) {            // 192 rows x 8 chunks = 1536 copies
        int id  = tid + j * GTHREADS;         // 0..1535
        int row = id >> 3, c = id & 7;
        if (row < TMd) {
            const __half* ga = &g_act[(size_t)(m0 + row) * KDIM + kk + c * 8];
            asm volatile("cp.async.cg.shared.global [%0], [%1], 16;"
                         :: "r"(sA + (uint32_t)(row * SROW_H + c * 8) * 2), "l"(ga));
        } else {
            int r2 = row - TMd;
            const __half* gb = &g_w[(size_t)(n0 + r2) * KDIM + kk + c * 8];
            asm volatile("cp.async.cg.shared.global [%0], [%1], 16;"
                         :: "r"(sB + (uint32_t)(r2 * SROW_H + c * 8) * 2), "l"(gb));
        }
    }
}

__global__ __launch_bounds__(GTHREADS, 2) void gemm_kernel() {
    extern __shared__ __align__(16) char smem[];
    const uint32_t sb = (uint32_t)__cvta_generic_to_shared(smem);
    int* s_unit = (int*)(smem + STAGES * STAGE_BYTES);
    const int tid = threadIdx.x;
    const int wid = tid >> 5, lane = tid & 31;
    const int g = lane >> 2, t = lane & 3;
    const int wm = wid >> 1, wn = wid & 1;     // 2 x 2 warp grid

    for (;;) {
        if (tid == 0) *s_unit = atomicAdd(&g_ctr, 1);
        __syncthreads();
        const int u = *s_unit;
        if (u >= NUNITS) break;
        const int m0  = (u >> 6) * TMd;         // 16 consecutive units share A strip
        const int ks  = (u >> 4) & 3;
        const int n0  = (u & 15) * TNd;
        const int kb0 = ks * KPER;

        float acc[4][4][4];
#pragma unroll
        for (int i = 0; i < 4; i++)
#pragma unroll
            for (int jj = 0; jj < 4; jj++)
#pragma unroll
                for (int r = 0; r < 4; r++) acc[i][jj][r] = 0.f;

#pragma unroll
        for (int s = 0; s < STAGES - 1; s++) {
            issue_stage(sb, s, s, m0, n0, kb0, tid);
            asm volatile("cp.async.commit_group;");
        }

        const int aRow = wm * 64 + g;
        const int bRow = wn * 32 + g;

        for (int it = 0; it < ITERSU; ++it) {
            asm volatile("cp.async.wait_group %0;" :: "n"(STAGES - 2));
            __syncthreads();
            if (it + STAGES - 1 < ITERSU)
                issue_stage(sb, (it + STAGES - 1) % STAGES, it + STAGES - 1,
                            m0, n0, kb0, tid);
            asm volatile("cp.async.commit_group;");

            const int buf = it % STAGES;
            const __half* As = (const __half*)(smem + buf * STAGE_BYTES);
            const __half* Bs = (const __half*)(smem + buf * STAGE_BYTES + A_BYTES);

#pragma unroll
            for (int kb = 0; kb < CHUNK; kb += 16) {
                uint32_t af[4][4], bf[4][2];
#pragma unroll
                for (int mi = 0; mi < 4; mi++) {
                    int r = aRow + mi * 16;
                    af[mi][0] = *(const uint32_t*)&As[r * SROW_H + kb + 2 * t];
                    af[mi][1] = *(const uint32_t*)&As[(r + 8) * SROW_H + kb + 2 * t];
                    af[mi][2] = *(const uint32_t*)&As[r * SROW_H + kb + 2 * t + 8];
                    af[mi][3] = *(const uint32_t*)&As[(r + 8) * SROW_H + kb + 2 * t + 8];
                }
#pragma unroll
                for (int ni = 0; ni < 4; ni++) {
                    int r = bRow + ni * 8;
                    bf[ni][0] = *(const uint32_t*)&Bs[r * SROW_H + kb + 2 * t];
                    bf[ni][1] = *(const uint32_t*)&Bs[r * SROW_H + kb + 2 * t + 8];
                }
#pragma unroll
                for (int mi = 0; mi < 4; mi++)
#pragma unroll
                    for (int ni = 0; ni < 4; ni++) {
                        asm volatile(
                            "mma.sync.aligned.m16n8k16.row.col.f32.f16.f16.f32 "
                            "{%0,%1,%2,%3}, {%4,%5,%6,%7}, {%8,%9}, {%0,%1,%2,%3};"
                            : "+f"(acc[mi][ni][0]), "+f"(acc[mi][ni][1]),
                              "+f"(acc[mi][ni][2]), "+f"(acc[mi][ni][3])
                            : "r"(af[mi][0]), "r"(af[mi][1]),
                              "r"(af[mi][2]), "r"(af[mi][3]),
                              "r"(bf[ni][0]), "r"(bf[ni][1]));
                    }
            }
        }

        // Epilogue: write fp16 partial tile to g_part[ks]
        __half* part = g_part + (size_t)ks * BROWS * OUTF;
#pragma unroll
        for (int mi = 0; mi < 4; mi++)
#pragma unroll
            for (int ni = 0; ni < 4; ni++) {
                int row = m0 + wm * 64 + mi * 16 + g;
                int col = n0 + wn * 32 + ni * 8 + 2 * t;
                __half2 h0 = __floats2half2_rn(acc[mi][ni][0], acc[mi][ni][1]);
                __half2 h1 = __floats2half2_rn(acc[mi][ni][2], acc[mi][ni][3]);
                *(__half2*)&part[(size_t)row * OUTF + col]       = h0;
                *(__half2*)&part[(size_t)(row + 8) * OUTF + col] = h1;
            }
        // next-unit top-of-loop barrier protects smem stage reuse
    }
}

// ---------------------------------------------------------------------------
// Kernel 3: reduce fp16 partials -> fp32 out (convert before summing)
// ---------------------------------------------------------------------------
#define PL_U4 ((BROWS * OUTF) / 8)   // uint4 (8 halfs) per plane = 524288
__global__ __launch_bounds__(256) void reduce_kernel(float* __restrict__ out) {
    int i = blockIdx.x * 256 + threadIdx.x;   // group of 8 output elems
    const uint4* p = (const uint4*)g_part;
    uint4 a = p[i], b = p[i + PL_U4], c = p[i + 2 * PL_U4], d = p[i + 3 * PL_U4];

    float4 r0, r1;
    {
        float2 fa = __half22float2(*(__half2*)&a.x), fb = __half22float2(*(__half2*)&b.x);
        float2 fc = __half22float2(*(__half2*)&c.x), fd = __half22float2(*(__half2*)&d.x);
        r0.x = (fa.x + fb.x) + (fc.x + fd.x);
        r0.y = (fa.y + fb.y) + (fc.y + fd.y);
    }
    {
        float2 fa = __half22float2(*(__half2*)&a.y), fb = __half22float2(*(__half2*)&b.y);
        float2 fc = __half22float2(*(__half2*)&c.y), fd = __half22float2(*(__half2*)&d.y);
        r0.z = (fa.x + fb.x) + (fc.x + fd.x);
        r0.w = (fa.y + fb.y) + (fc.y + fd.y);
    }
    {
        float2 fa = __half22float2(*(__half2*)&a.z), fb = __half22float2(*(__half2*)&b.z);
        float2 fc = __half22float2(*(__half2*)&c.z), fd = __half22float2(*(__half2*)&d.z);
        r1.x = (fa.x + fb.x) + (fc.x + fd.x);
        r1.y = (fa.y + fb.y) + (fc.y + fd.y);
    }
    {
        float2 fa = __half22float2(*(__half2*)&a.w), fb = __half22float2(*(__half2*)&b.w);
        float2 fc = __half22float2(*(__half2*)&c.w), fd = __half22float2(*(__half2*)&d.w);
        r1.z = (fa.x + fb.x) + (fc.x + fd.x);
        r1.w = (fa.y + fb.y) + (fc.y + fd.y);
    }
    ((float4*)out)[2 * i]     = r0;
    ((float4*)out)[2 * i + 1] = r1;
}

// ---------------------------------------------------------------------------
extern "C" void kernel_launch(void* const* d_in, const int* in_sizes, int n_in,
                              void* d_out, int out_size) {
    const float* x    = (const float*)d_in[0];
    const float* bw   = (const float*)d_in[1];
    const float* sw   = (const float*)d_in[2];
    const float* grid = (const float*)d_in[3];
    float* out = (float*)d_out;

    cudaFuncSetAttribute(gemm_kernel, cudaFuncAttributeMaxDynamicSharedMemorySize,
                         SMEM_TOTAL);

    prep_kernel<<<ACT_BLOCKS + W_BLOCKS, 256>>>(x, grid, bw, sw);
    gemm_kernel<<<GCTAS, GTHREADS, SMEM_TOTAL>>>();
    reduce_kernel<<<PL_U4 / 256, 256>>>(out);
}